// round 13
// baseline (speedup 1.0000x reference)
#include <cuda_runtime.h>
#include <math.h>

#define NBOX   4096
#define RPB    128                      // pred rows per pair block
#define CHUNK  128                      // targets per pair block
#define NBLK   1024                     // 32x32 pair blocks
#define NCELL  64                       // 8x8 spatial cells (100px), morton order

// Scratch (device globals: no allocation allowed in kernel_launch)
__device__ int    g_cnt[2 * NCELL];     // per-side per-cell counts
__device__ float4 g_sP4[NBOX];          // spatially sorted preds
__device__ int    g_sPi[NBOX];          // original indices
__device__ float4 g_sT4[NBOX];          // spatially sorted targets
__device__ int    g_sTi[NBOX];
__device__ unsigned long long g_best[NBOX]; // packed (ratio_bits<<32 | ~argOrig); 0 = none
__device__ float  g_rbS[NBLK];
__device__ int    g_rbC[NBLK];
__device__ double g_pG[32];             // per-bx RepGT sln partials
__device__ int    g_pC[32];             // per-bx RepGT counts
__device__ double g_pL[4];              // smooth-L1 partials (sort pred blocks)
__device__ unsigned int g_bxT[32];      // per-bx pair tickets
__device__ unsigned int g_ticket;       // global pair ticket

__device__ __forceinline__ int cellOf(float x, float y) {
    int cx = (int)(x * 0.01f); cx = cx < 0 ? 0 : (cx > 7 ? 7 : cx);
    int cy = (int)(y * 0.01f); cy = cy < 0 ? 0 : (cy > 7 ? 7 : cy);
    return (cx & 1) | ((cy & 1) << 1) | ((cx & 2) << 1) |
           ((cy & 2) << 2) | ((cx & 4) << 2) | ((cy & 4) << 3);
}

// ---------------------------------------------------------------------------
// Kernel 0: fused rank + scatter + sl1. 8 blocks x 1024 as TWO 4-CTA
// clusters (cluster == side). Parallel 64-entry prefix scan (no serial loop).
// ---------------------------------------------------------------------------
__global__ __launch_bounds__(1024) __cluster_dims__(4, 1, 1)
void sort_kernel(const float4* __restrict__ pred4,
                 const float4* __restrict__ tgt4)
{
    const int tid  = threadIdx.x;
    const int side = blockIdx.x >> 2;               // 0 = tgt, 1 = pred
    const int idx  = (blockIdx.x & 3) * 1024 + tid;
    const float4* src = side ? pred4 : tgt4;
    float4* dst  = side ? g_sP4 : g_sT4;
    int*    dsti = side ? g_sPi : g_sTi;
    const int lane = tid & 31, wrp = tid >> 5;

    __shared__ int sh[NCELL], sbase[NCELL], sscan[NCELL];
    if (tid < NCELL) sh[tid] = 0;
    __syncthreads();

    const float4 v = src[idx];
    const int cell = cellOf(v.x, v.y);
    const int lr   = atomicAdd(&sh[cell], 1);
    __syncthreads();
    if (tid < NCELL) sbase[tid] = atomicAdd(&g_cnt[side * NCELL + tid], sh[tid]);
    __syncthreads();
    const int rank = sbase[cell] + lr;

    // smooth-L1 partial on pred-side blocks: elements [4*idx, 4*idx+4)
    if (side) {
        const float4 tv = tgt4[idx];
        float slf = 0.0f, d;
        d = fabsf(v.x - tv.x); slf += (d < 1.0f) ? 0.5f * d * d : d - 0.5f;
        d = fabsf(v.y - tv.y); slf += (d < 1.0f) ? 0.5f * d * d : d - 0.5f;
        d = fabsf(v.z - tv.z); slf += (d < 1.0f) ? 0.5f * d * d : d - 0.5f;
        d = fabsf(v.w - tv.w); slf += (d < 1.0f) ? 0.5f * d * d : d - 0.5f;
        double sl = (double)slf;
        #pragma unroll
        for (int o = 16; o > 0; o >>= 1) sl += __shfl_down_sync(0xffffffffu, sl, o);
        __shared__ double sWL[32];
        if (lane == 0) sWL[wrp] = sl;
        __syncthreads();
        if (tid == 0) {
            double a = 0.0;
            #pragma unroll
            for (int w = 0; w < 32; ++w) a += sWL[w];
            g_pL[blockIdx.x - 4] = a;
        }
    }

    // ---- cluster barrier: all 4 blocks of this side have added their counts
    __threadfence();
    asm volatile("barrier.cluster.arrive.aligned;" ::: "memory");
    asm volatile("barrier.cluster.wait.aligned;" ::: "memory");

    // parallel inclusive scan of final per-cell counts (Hillis-Steele, 6 steps)
    int myCnt = 0;
    if (tid < NCELL) { myCnt = g_cnt[side * NCELL + tid]; sscan[tid] = myCnt; }
    __syncthreads();
    #pragma unroll
    for (int o = 1; o < NCELL; o <<= 1) {
        int add = 0;
        if (tid < NCELL && tid >= o) add = sscan[tid - o];
        __syncthreads();
        if (tid < NCELL) sscan[tid] += add;
        __syncthreads();
    }
    // exclusive offset for my cell = inclusive - count
    const int pos = (sscan[cell] - sh[cell] - sbase[cell] + rank);
    // note: exclusive base for cell = sscan[cell] - totalCnt[cell]; rank is the
    // element's global rank within the cell. totalCnt = sscan diff; but we only
    // have per-block sh and base. Use: exclusive = sscan[cell] - cntFinal[cell].
    // cntFinal[cell] is loaded below via sscan reconstruction:
    // (handled correctly because rank < cntFinal and
    //  exclusive = sscan[cell] - cntFinal[cell])
    __syncthreads();

    // recompute exclusive properly: need final count of my cell
    __shared__ int sfin[NCELL];
    if (tid < NCELL) sfin[tid] = g_cnt[side * NCELL + tid];
    __syncthreads();
    const int posOK = sscan[cell] - sfin[cell] + rank;

    dst[posOK]  = v;
    dsti[posOK] = idx;
    (void)pos;
}

// ---------------------------------------------------------------------------
// Kernel 1: pair sweep + compaction + distributed RepGT finalize (per-bx
// ticket) + final reduce/broadcast (global ticket). Single kernel tail
// replaces the combine kernel entirely.
// ---------------------------------------------------------------------------
__global__ __launch_bounds__(RPB)
void pair_kernel(const float4* __restrict__ pred4,
                 const float4* __restrict__ tgt4,
                 float* __restrict__ out)
{
    const int tid = threadIdx.x;
    const int bx = blockIdx.x, by = blockIdx.y;
    const int b  = bx * 32 + by;
    const int lane = tid & 31, wrp = tid >> 5;

    __shared__ float4 sT2[CHUNK];
    __shared__ float2 sAJ2[CHUNK];
    __shared__ float4 sPB[4];
    __shared__ int sCnt[4], sBase[4], sN;
    __shared__ unsigned int sBxLast, sGlobLast;

    // --- own pred row + warp bbox ---
    const int r = bx * RPB + tid;
    float4 p = g_sP4[r];
    const int iO = g_sPi[r];
    const float areaP = (p.z - p.x + 1.0f) * (p.w - p.y + 1.0f);
    p.z += 1.0f; p.w += 1.0f;

    {
        float mnx = p.x, mxx = p.z, mny = p.y, mxy = p.w;
        #pragma unroll
        for (int o = 16; o > 0; o >>= 1) {
            mnx = fminf(mnx, __shfl_xor_sync(0xffffffffu, mnx, o));
            mxx = fmaxf(mxx, __shfl_xor_sync(0xffffffffu, mxx, o));
            mny = fminf(mny, __shfl_xor_sync(0xffffffffu, mny, o));
            mxy = fmaxf(mxy, __shfl_xor_sync(0xffffffffu, mxy, o));
        }
        if (lane == 0) sPB[wrp] = make_float4(mnx, mxx, mny, mxy);
    }
    __syncthreads();

    const float pmnx = fminf(fminf(sPB[0].x, sPB[1].x), fminf(sPB[2].x, sPB[3].x));
    const float pmxx = fmaxf(fmaxf(sPB[0].y, sPB[1].y), fmaxf(sPB[2].y, sPB[3].y));
    const float pmny = fminf(fminf(sPB[0].z, sPB[1].z), fminf(sPB[2].z, sPB[3].z));
    const float pmxy = fmaxf(fmaxf(sPB[0].w, sPB[1].w), fmaxf(sPB[2].w, sPB[3].w));

    // --- load my target, test vs block bbox, deterministic compaction ---
    {
        float4 t = g_sT4[by * CHUNK + tid];
        const int jO = g_sTi[by * CHUNK + tid];
        const float a = (t.z - t.x + 1.0f) * (t.w - t.y + 1.0f);
        t.z += 1.0f; t.w += 1.0f;
        const bool pass = (pmxx > t.x) && (t.z > pmnx) &&
                          (pmxy > t.y) && (t.w > pmny);
        const unsigned m = __ballot_sync(0xffffffffu, pass);
        if (lane == 0) sCnt[wrp] = __popc(m);
        __syncthreads();
        if (tid == 0) {
            int acc = 0;
            #pragma unroll
            for (int w = 0; w < 4; ++w) { sBase[w] = acc; acc += sCnt[w]; }
            sN = acc;
        }
        __syncthreads();
        if (pass) {
            const int pos = sBase[wrp] + __popc(m & ((1u << lane) - 1u));
            sT2[pos]  = t;
            sAJ2[pos] = make_float2(a, __int_as_float(jO));
        }
    }
    __syncthreads();

    const int nAct = sN;
    {
        float bI = 0.0f, bU = 1.0f;
        int   bA = 0;
        float rbS = 0.0f;
        int   rbC = 0;

        #pragma unroll 4
        for (int k = 0; k < nAct; ++k) {
            const float4 t  = sT2[k];
            const float2 aj = sAJ2[k];
            float iw = fminf(p.z, t.z) - fmaxf(p.x, t.x);
            float ih = fminf(p.w, t.w) - fmaxf(p.y, t.y);
            iw = fmaxf(iw, 0.0f);
            ih = fmaxf(ih, 0.0f);
            const float inter = iw * ih;
            const float ua    = areaP + aj.x - inter;
            const int   jO    = __float_as_int(aj.y);
            if ((jO != iO) && (inter * bU > bI * ua)) {
                bI = inter; bU = ua; bA = jO;
            }
            if ((jO < iO) && (inter > 0.0f)) {
                rbS += __fdividef(inter, ua);
                rbC += 1;
            }
        }

        if (bI > 0.0f) {
            const float ratio = bI / bU;
            const unsigned long long packed =
                ((unsigned long long)__float_as_uint(ratio) << 32) |
                (unsigned long long)(0xFFFFFFFFu - (unsigned)bA);
            atomicMax(&g_best[iO], packed);
        }

        #pragma unroll
        for (int o = 16; o > 0; o >>= 1) {
            rbS += __shfl_down_sync(0xffffffffu, rbS, o);
            rbC += __shfl_down_sync(0xffffffffu, rbC, o);
        }
        __shared__ float wS[4];
        __shared__ int   wC[4];
        if (lane == 0) { wS[wrp] = rbS; wC[wrp] = rbC; }
        __syncthreads();
        if (tid == 0) {
            float s = 0.0f; int c = 0;
            #pragma unroll
            for (int w = 0; w < 4; ++w) { s += wS[w]; c += wC[w]; }
            g_rbS[b] = s;
            g_rbC[b] = c;
        }
    }

    // ---- per-bx ticket: last of 32 finalizes this pred chunk's RepGT ----
    __syncthreads();
    if (tid == 0) {
        __threadfence();
        sBxLast = (atomicAdd(&g_bxT[bx], 1u) == 31u) ? 1u : 0u;
    }
    __syncthreads();

    if (sBxLast) {
        const unsigned long long packed = __ldcg(&g_best[iO]);
        g_best[iO] = 0ull;                  // reset for next replay

        float sgf = 0.0f;
        int   cgi = 0;
        if (packed != 0ull) {
            const int bA2 = (int)(0xFFFFFFFFu - (unsigned)(packed & 0xFFFFFFFFull));
            const float4 pe = pred4[iO];
            const float4 g  = tgt4[bA2];
            const float iw = fmaxf(fminf(pe.z, g.z) - fmaxf(pe.x, g.x), 0.0f);
            const float ih = fmaxf(fminf(pe.w, g.w) - fmaxf(pe.y, g.y), 0.0f);
            const float garea = (g.z - g.x) * (g.w - g.y);
            const float iog = iw * ih / garea;      // no +1 for IoG
            if (iog > 0.9f) {
                sgf = (iog - 0.9f) / (1.0f - 0.9f) + 2.3025851f;
            } else {
                const float xc = fminf(fmaxf(iog, 0.0f), 1.0f - 1e-6f);
                sgf = -log1pf(-xc);
            }
            cgi = 1;
        }
        double sg = (double)sgf;
        int cg = cgi;
        #pragma unroll
        for (int o = 16; o > 0; o >>= 1) {
            sg += __shfl_down_sync(0xffffffffu, sg, o);
            cg += __shfl_down_sync(0xffffffffu, cg, o);
        }
        __shared__ double fG[4];
        __shared__ int    fC[4];
        if (lane == 0) { fG[wrp] = sg; fC[wrp] = cg; }
        __syncthreads();
        if (tid == 0) {
            double tg = 0.0; int tc = 0;
            #pragma unroll
            for (int w = 0; w < 4; ++w) { tg += fG[w]; tc += fC[w]; }
            g_pG[bx] = tg;
            g_pC[bx] = tc;
            g_bxT[bx] = 0u;                 // reset for next replay
        }
    }

    // ---- global ticket: 1024th block does final reduce + broadcast ----
    __syncthreads();
    if (tid == 0) {
        __threadfence();
        sGlobLast = (atomicAdd(&g_ticket, 1u) == NBLK - 1u) ? 1u : 0u;
    }
    __syncthreads();
    if (sGlobLast == 0u) return;

    {
        double trb = 0.0, tsg = 0.0, tsl = 0.0;
        long long tcb = 0; int tcg = 0;
        #pragma unroll
        for (int q = 0; q < NBLK / RPB; ++q) {      // 8 rb partials per thread
            const int bb = q * RPB + tid;
            trb += (double)__ldcg(&g_rbS[bb]);
            tcb += (long long)__ldcg(&g_rbC[bb]);
        }
        if (tid < 32) { tsg = __ldcg(&g_pG[tid]); tcg = __ldcg(&g_pC[tid]); }
        if (tid < 4)  { tsl = __ldcg(&g_pL[tid]); }
        if (tid < 2 * NCELL) g_cnt[tid] = 0;        // reset for next replay
        if (tid == 0) g_ticket = 0u;

        #pragma unroll
        for (int o = 16; o > 0; o >>= 1) {
            trb += __shfl_down_sync(0xffffffffu, trb, o);
            tcb += __shfl_down_sync(0xffffffffu, tcb, o);
            tsg += __shfl_down_sync(0xffffffffu, tsg, o);
            tsl += __shfl_down_sync(0xffffffffu, tsl, o);
            tcg += __shfl_down_sync(0xffffffffu, tcg, o);
        }
        __shared__ double hR[4], hG[4], hL[4];
        __shared__ long long hB[4];
        __shared__ int hC[4];
        __shared__ float sScalar;
        if (lane == 0) { hR[wrp] = trb; hB[wrp] = tcb; hG[wrp] = tsg;
                         hL[wrp] = tsl; hC[wrp] = tcg; }
        __syncthreads();
        if (tid == 0) {
            double ar = 0.0, ag = 0.0, al = 0.0;
            long long ab = 0; int ac = 0;
            #pragma unroll
            for (int w = 0; w < 4; ++w) {
                ar += hR[w]; ab += hB[w]; ag += hG[w]; al += hL[w]; ac += hC[w];
            }
            const float sl1    = (float)(al / (double)(NBOX * 4));
            const float repgt  = (ac > 0) ? (float)(ag / (double)ac) : 0.0f;
            const float repbox = (ab > 0) ? (float)(ar / (double)ab) : 0.0f;
            sScalar = sl1 + repgt + repbox;
        }
        __syncthreads();

        const float s = sScalar;
        float4* out4 = (float4*)out;
        const float4 v = make_float4(s, s, s, s);
        #pragma unroll
        for (int q = 0; q < NBOX / 4 / RPB; ++q)    // 8 float4 per thread
            out4[q * RPB + tid] = v;
    }
}

// ---------------------------------------------------------------------------
extern "C" void kernel_launch(void* const* d_in, const int* in_sizes, int n_in,
                              void* d_out, int out_size)
{
    const float* pred = (const float*)d_in[0];
    const float* tgt  = (const float*)d_in[1];
    float* out = (float*)d_out;

    sort_kernel<<<8, 1024>>>((const float4*)pred, (const float4*)tgt);
    dim3 grid(32, 32);
    pair_kernel<<<grid, RPB>>>((const float4*)pred, (const float4*)tgt, out);
}